// round 2
// baseline (speedup 1.0000x reference)
#include <cuda_runtime.h>
#include <cstdint>

// Problem constants
#define NN   100000   // nodes
#define RR   4        // relations
#define EE   500000   // edges per relation
#define INF  256
#define HIDF 128
#define OUTF 64

// ---------------------------------------------------------------------------
// Static device scratch (allocation-free per harness rules)
// ---------------------------------------------------------------------------
static __device__ float g_Y1[(size_t)NN * RR * HIDF];   // layer-1 GEMM out, concat cols (204.8 MB)
static __device__ float g_Y2[(size_t)NN * RR * OUTF];   // layer-2 GEMM out, concat cols (102.4 MB)
static __device__ float g_acc1[(size_t)NN * HIDF];      // layer-1 result (post-ReLU)     (51.2 MB)
static __device__ int   g_cnt_out[RR * NN];             // out-degree counts
static __device__ int   g_cnt_in[RR * NN];              // in-degree counts
static __device__ float g_rs_out[RR * NN];              // rsqrt(out-degree)
static __device__ float g_rs_in[RR * NN];               // rsqrt(in-degree)
static __device__ int   g_offs[RR * NN];                // CSR segment starts (relation-local)
static __device__ int   g_cur[RR * NN];                 // fill cursors
static __device__ int   g_relctr[RR];                   // per-relation bump allocators
static __device__ int2  g_csr[(size_t)RR * EE];         // (src, bits(rs_out_r[src])) per edge

// ---------------------------------------------------------------------------
// f32x2 packed-FMA helpers (Blackwell sm_103a: 2x fp32 throughput vs FFMA)
// ---------------------------------------------------------------------------
__device__ __forceinline__ unsigned long long pack2(float x) {
    unsigned long long r;
    asm("mov.b64 %0, {%1, %1};" : "=l"(r) : "f"(x));
    return r;
}
__device__ __forceinline__ void fma2(unsigned long long& c,
                                     unsigned long long a,
                                     unsigned long long b) {
    asm("fma.rn.f32x2 %0, %1, %2, %0;" : "+l"(c) : "l"(a), "l"(b));
}
__device__ __forceinline__ void unpack2(unsigned long long c, float& lo, float& hi) {
    asm("mov.b64 {%0, %1}, %2;" : "=f"(lo), "=f"(hi) : "l"(c));
}

// ---------------------------------------------------------------------------
// Graph preprocessing kernels
// ---------------------------------------------------------------------------
__global__ void degree_count_kernel(const int* __restrict__ src,
                                    const int* __restrict__ dst,
                                    int* __restrict__ cnt_out,
                                    int* __restrict__ cnt_in) {
    int i = blockIdx.x * blockDim.x + threadIdx.x;
    if (i >= RR * EE) return;
    int r = i / EE;
    atomicAdd(&cnt_out[r * NN + src[i]], 1);
    atomicAdd(&cnt_in [r * NN + dst[i]], 1);
}

__global__ void rs_kernel(const int* __restrict__ cnt_out,
                          const int* __restrict__ cnt_in,
                          float* __restrict__ rs_out,
                          float* __restrict__ rs_in) {
    int i = blockIdx.x * blockDim.x + threadIdx.x;
    if (i >= RR * NN) return;
    rs_out[i] = rsqrtf((float)max(cnt_out[i], 1));
    rs_in [i] = rsqrtf((float)max(cnt_in [i], 1));
}

// Segment allocation: contiguous ranges per (relation, dst) in arbitrary order.
__global__ void alloc_offsets_kernel(const int* __restrict__ cnt_in,
                                     int* __restrict__ offs,
                                     int* __restrict__ cur,
                                     int* __restrict__ relctr) {
    int i = blockIdx.x * blockDim.x + threadIdx.x;
    if (i >= RR * NN) return;
    int r = i / NN;
    int c = cnt_in[i];
    int off = atomicAdd(&relctr[r], c);
    offs[i] = off;
    cur[i]  = off;
}

__global__ void csr_fill_kernel(const int* __restrict__ src,
                                const int* __restrict__ dst,
                                const float* __restrict__ rs_out,
                                int* __restrict__ cur,
                                int2* __restrict__ csr) {
    int i = blockIdx.x * blockDim.x + threadIdx.x;
    if (i >= RR * EE) return;
    int r = i / EE;
    int s = src[i];
    int d = dst[i];
    int pos = atomicAdd(&cur[r * NN + d], 1);
    csr[(size_t)r * EE + pos] = make_int2(s, __float_as_int(rs_out[r * NN + s]));
}

// ---------------------------------------------------------------------------
// GEMM:  H[m, c0 + 0:BN] = X[m, :] @ W[:, 0:BN]    (H has row stride ld)
// BM=128, BK=16, 256 threads, TM=8 rows x TN cols per thread, f32x2 FMAs.
// ---------------------------------------------------------------------------
template <int BN, int TN>
__global__ __launch_bounds__(256, 2)
void gemm_kernel(const float* __restrict__ X,
                 const float* __restrict__ W,
                 float* __restrict__ H,       // pre-offset to column block
                 int M, int K, int ld) {
    constexpr int BM = 128;
    constexpr int BK = 16;
    constexpr int TM = 8;
    constexpr int NTH = 256;

    __shared__ __align__(16) float As[BK][BM + 4];
    __shared__ __align__(16) float Bs[BK][BN];

    const int t = threadIdx.x;
    const int rowBase = blockIdx.x * BM;

    const int tr = t / (BN / TN);
    const int tc = t % (BN / TN);
    const int r0 = tr * TM;
    const int c0 = tc * TN;

    unsigned long long acc[TM][TN / 2];
#pragma unroll
    for (int i = 0; i < TM; ++i)
#pragma unroll
        for (int j = 0; j < TN / 2; ++j) acc[i][j] = 0ull;

    for (int k0 = 0; k0 < K; k0 += BK) {
        constexpr int A4 = BM * BK / 4;
#pragma unroll
        for (int i = 0; i < A4 / NTH; ++i) {
            int id = t + i * NTH;
            int row = id / (BK / 4);
            int kk4 = id % (BK / 4);
            int grow = rowBase + row;
            float4 v = make_float4(0.f, 0.f, 0.f, 0.f);
            if (grow < M)
                v = *reinterpret_cast<const float4*>(X + (size_t)grow * K + k0 + kk4 * 4);
            As[kk4 * 4 + 0][row] = v.x;
            As[kk4 * 4 + 1][row] = v.y;
            As[kk4 * 4 + 2][row] = v.z;
            As[kk4 * 4 + 3][row] = v.w;
        }
        constexpr int B4 = BK * BN / 4;
#pragma unroll
        for (int i = 0; i < (B4 + NTH - 1) / NTH; ++i) {
            int id = t + i * NTH;
            if ((B4 % NTH == 0) || (id < B4)) {
                int kk = id / (BN / 4);
                int c4 = id % (BN / 4);
                float4 v = *reinterpret_cast<const float4*>(W + (size_t)(k0 + kk) * BN + c4 * 4);
                *reinterpret_cast<float4*>(&Bs[kk][c4 * 4]) = v;
            }
        }
        __syncthreads();

#pragma unroll
        for (int kk = 0; kk < BK; ++kk) {
            float a[TM];
#pragma unroll
            for (int i = 0; i < TM; i += 4) {
                float4 av = *reinterpret_cast<const float4*>(&As[kk][r0 + i]);
                a[i] = av.x; a[i + 1] = av.y; a[i + 2] = av.z; a[i + 3] = av.w;
            }
            unsigned long long b[TN / 2];
#pragma unroll
            for (int j = 0; j < TN / 2; j += 2) {
                ulonglong2 bv = *reinterpret_cast<const ulonglong2*>(&Bs[kk][c0 + j * 2]);
                b[j] = bv.x; b[j + 1] = bv.y;
            }
#pragma unroll
            for (int i = 0; i < TM; ++i) {
                unsigned long long ad = pack2(a[i]);
#pragma unroll
                for (int j = 0; j < TN / 2; ++j) fma2(acc[i][j], ad, b[j]);
            }
        }
        __syncthreads();
    }

#pragma unroll
    for (int i = 0; i < TM; ++i) {
        int grow = rowBase + r0 + i;
        if (grow < M) {
            float* Hrow = H + (size_t)grow * ld + c0;
#pragma unroll
            for (int j = 0; j < TN / 2; ++j) {
                float lo, hi;
                unpack2(acc[i][j], lo, hi);
                reinterpret_cast<float2*>(Hrow)[j] = make_float2(lo, hi);
            }
        }
    }
}

// ---------------------------------------------------------------------------
// Gather (layer 1, F=128): warp per dst node, 4 floats per lane.
// acc1[d] = relu( sum_r rs_in_r[d] * sum_{e in CSR_r[d]} w_e * Y1[src_e, r*128:*] + sum_r b1[r] )
// ---------------------------------------------------------------------------
__global__ __launch_bounds__(256)
void gather_l1_kernel(const float* __restrict__ Y,
                      const int2* __restrict__ csr,
                      const int* __restrict__ offs,
                      const int* __restrict__ cnt,
                      const float* __restrict__ rs_in,
                      const float* __restrict__ b1,
                      float* __restrict__ acc1) {
    int d = (blockIdx.x * blockDim.x + threadIdx.x) >> 5;
    int lane = threadIdx.x & 31;
    if (d >= NN) return;
    float4 tot = make_float4(0.f, 0.f, 0.f, 0.f);
#pragma unroll
    for (int r = 0; r < RR; ++r) {
        int start = offs[r * NN + d];
        int n     = cnt [r * NN + d];
        const int2* ep = csr + (size_t)r * EE + start;
        const float* Yr = Y + r * HIDF + lane * 4;
        float4 part = make_float4(0.f, 0.f, 0.f, 0.f);
        for (int e = 0; e < n; ++e) {
            int2 ew = __ldg(ep + e);
            float w = __int_as_float(ew.y);
            float4 v = *reinterpret_cast<const float4*>(Yr + (size_t)ew.x * (RR * HIDF));
            part.x += w * v.x; part.y += w * v.y;
            part.z += w * v.z; part.w += w * v.w;
        }
        float ri = rs_in[r * NN + d];
        tot.x += ri * part.x; tot.y += ri * part.y;
        tot.z += ri * part.z; tot.w += ri * part.w;
    }
#pragma unroll
    for (int r = 0; r < RR; ++r) {
        float4 bv = *reinterpret_cast<const float4*>(b1 + r * HIDF + lane * 4);
        tot.x += bv.x; tot.y += bv.y; tot.z += bv.z; tot.w += bv.w;
    }
    tot.x = fmaxf(tot.x, 0.f); tot.y = fmaxf(tot.y, 0.f);
    tot.z = fmaxf(tot.z, 0.f); tot.w = fmaxf(tot.w, 0.f);
    *reinterpret_cast<float4*>(acc1 + (size_t)d * HIDF + lane * 4) = tot;
}

// ---------------------------------------------------------------------------
// Gather (layer 2, F=64): warp per dst node, 2 floats per lane. Writes output.
// ---------------------------------------------------------------------------
__global__ __launch_bounds__(256)
void gather_l2_kernel(const float* __restrict__ Y,
                      const int2* __restrict__ csr,
                      const int* __restrict__ offs,
                      const int* __restrict__ cnt,
                      const float* __restrict__ rs_in,
                      const float* __restrict__ b2,
                      float* __restrict__ out) {
    int d = (blockIdx.x * blockDim.x + threadIdx.x) >> 5;
    int lane = threadIdx.x & 31;
    if (d >= NN) return;
    float2 tot = make_float2(0.f, 0.f);
#pragma unroll
    for (int r = 0; r < RR; ++r) {
        int start = offs[r * NN + d];
        int n     = cnt [r * NN + d];
        const int2* ep = csr + (size_t)r * EE + start;
        const float* Yr = Y + r * OUTF + lane * 2;
        float2 part = make_float2(0.f, 0.f);
        for (int e = 0; e < n; ++e) {
            int2 ew = __ldg(ep + e);
            float w = __int_as_float(ew.y);
            float2 v = *reinterpret_cast<const float2*>(Yr + (size_t)ew.x * (RR * OUTF));
            part.x += w * v.x; part.y += w * v.y;
        }
        float ri = rs_in[r * NN + d];
        tot.x += ri * part.x; tot.y += ri * part.y;
    }
#pragma unroll
    for (int r = 0; r < RR; ++r) {
        float2 bv = *reinterpret_cast<const float2*>(b2 + r * OUTF + lane * 2);
        tot.x += bv.x; tot.y += bv.y;
    }
    *reinterpret_cast<float2*>(out + (size_t)d * OUTF + lane * 2) = tot;
}

// ---------------------------------------------------------------------------
// Launch
// ---------------------------------------------------------------------------
extern "C" void kernel_launch(void* const* d_in, const int* in_sizes, int n_in,
                              void* d_out, int out_size) {
    const float* x    = (const float*)d_in[0];
    const int*   esrc = (const int*)  d_in[1];
    const int*   edst = (const int*)  d_in[2];
    const float* W1   = (const float*)d_in[3];
    const float* b1   = (const float*)d_in[4];
    const float* W2   = (const float*)d_in[5];
    const float* b2   = (const float*)d_in[6];
    float* out = (float*)d_out;

    float *Y1, *Y2, *acc1, *rs_out, *rs_in;
    int *cnt_out, *cnt_in, *offs, *cur, *relctr;
    int2* csr;
    cudaGetSymbolAddress((void**)&Y1,      g_Y1);
    cudaGetSymbolAddress((void**)&Y2,      g_Y2);
    cudaGetSymbolAddress((void**)&acc1,    g_acc1);
    cudaGetSymbolAddress((void**)&cnt_out, g_cnt_out);
    cudaGetSymbolAddress((void**)&cnt_in,  g_cnt_in);
    cudaGetSymbolAddress((void**)&rs_out,  g_rs_out);
    cudaGetSymbolAddress((void**)&rs_in,   g_rs_in);
    cudaGetSymbolAddress((void**)&offs,    g_offs);
    cudaGetSymbolAddress((void**)&cur,     g_cur);
    cudaGetSymbolAddress((void**)&relctr,  g_relctr);
    cudaGetSymbolAddress((void**)&csr,     g_csr);

    const int TPB = 256;

    // ---- CSR build + degree normalizers ----
    cudaMemsetAsync(cnt_out, 0, RR * NN * sizeof(int));
    cudaMemsetAsync(cnt_in,  0, RR * NN * sizeof(int));
    cudaMemsetAsync(relctr,  0, RR * sizeof(int));
    degree_count_kernel<<<(RR * EE + TPB - 1) / TPB, TPB>>>(esrc, edst, cnt_out, cnt_in);
    rs_kernel<<<(RR * NN + TPB - 1) / TPB, TPB>>>(cnt_out, cnt_in, rs_out, rs_in);
    alloc_offsets_kernel<<<(RR * NN + TPB - 1) / TPB, TPB>>>(cnt_in, offs, cur, relctr);
    csr_fill_kernel<<<(RR * EE + TPB - 1) / TPB, TPB>>>(esrc, edst, rs_out, cur, csr);

    const int gemmGrid   = (NN + 127) / 128;           // 782
    const int gatherGrid = (NN * 32 + TPB - 1) / TPB;  // warp per dst

    // ---- Layer 1: Y1[:, r*128:(r+1)*128] = x @ W1_r ; then gather ----
    for (int r = 0; r < RR; ++r) {
        gemm_kernel<HIDF, 8><<<gemmGrid, TPB>>>(
            x, W1 + (size_t)r * INF * HIDF, Y1 + r * HIDF, NN, INF, RR * HIDF);
    }
    gather_l1_kernel<<<gatherGrid, TPB>>>(Y1, csr, offs, cnt_in, rs_in, b1, acc1);

    // ---- Layer 2: Y2[:, r*64:(r+1)*64] = relu_acc1 @ W2_r ; then gather ----
    for (int r = 0; r < RR; ++r) {
        gemm_kernel<OUTF, 4><<<gemmGrid, TPB>>>(
            acc1, W2 + (size_t)r * HIDF * OUTF, Y2 + r * OUTF, NN, HIDF, RR * OUTF);
    }
    gather_l2_kernel<<<gatherGrid, TPB>>>(Y2, csr, offs, cnt_in, rs_in, b2, out);
}

// round 6
// speedup vs baseline: 2.2962x; 2.2962x over previous
#include <cuda_runtime.h>
#include <cuda_bf16.h>
#include <cstdint>

// Problem constants
#define NN   100000   // nodes
#define RR   4        // relations
#define EE   500000   // edges per relation
#define INF  256
#define HIDF 128
#define OUTF 64

// ---------------------------------------------------------------------------
// Static device scratch (allocation-free per harness rules)
// ---------------------------------------------------------------------------
static __device__ __nv_bfloat16 g_xhi[(size_t)NN * INF];     // 51.2 MB
static __device__ __nv_bfloat16 g_xlo[(size_t)NN * INF];     // 51.2 MB
static __device__ __nv_bfloat16 g_w1hi[RR * INF * HIDF];
static __device__ __nv_bfloat16 g_w1lo[RR * INF * HIDF];
static __device__ __nv_bfloat16 g_w2hi[RR * HIDF * OUTF];
static __device__ __nv_bfloat16 g_w2lo[RR * HIDF * OUTF];
static __device__ __nv_bfloat16 g_a2hi[(size_t)NN * HIDF];   // 25.6 MB
static __device__ __nv_bfloat16 g_a2lo[(size_t)NN * HIDF];   // 25.6 MB
static __device__ float g_Y1[(size_t)RR * NN * HIDF];        // 204.8 MB  [r][n][128]
static __device__ float g_Y2[(size_t)RR * NN * OUTF];        // 102.4 MB  [r][n][64]
static __device__ float g_acc1[(size_t)NN * HIDF];           // 51.2 MB
static __device__ float g_rs[2 * RR * NN];                   // [out | in]

// ---------------------------------------------------------------------------
// Tensor-core primitives (sm_80+ mma.sync, bf16 -> f32)
// ---------------------------------------------------------------------------
__device__ __forceinline__ void ldsm_x4(uint32_t* r, uint32_t a) {
    asm volatile("ldmatrix.sync.aligned.m8n8.x4.shared.b16 {%0,%1,%2,%3}, [%4];"
                 : "=r"(r[0]), "=r"(r[1]), "=r"(r[2]), "=r"(r[3]) : "r"(a));
}
__device__ __forceinline__ void ldsm_x2t(uint32_t* r, uint32_t a) {
    asm volatile("ldmatrix.sync.aligned.m8n8.x2.trans.shared.b16 {%0,%1}, [%2];"
                 : "=r"(r[0]), "=r"(r[1]) : "r"(a));
}
__device__ __forceinline__ void mma16816(float* c, const uint32_t* a, const uint32_t* b) {
    asm volatile(
        "mma.sync.aligned.m16n8k16.row.col.f32.bf16.bf16.f32 "
        "{%0,%1,%2,%3}, {%4,%5,%6,%7}, {%8,%9}, {%0,%1,%2,%3};"
        : "+f"(c[0]), "+f"(c[1]), "+f"(c[2]), "+f"(c[3])
        : "r"(a[0]), "r"(a[1]), "r"(a[2]), "r"(a[3]), "r"(b[0]), "r"(b[1]));
}

// ---------------------------------------------------------------------------
// Preprocessing kernels
// ---------------------------------------------------------------------------
__global__ void fzero_kernel(float* p, int n) {
    int i = blockIdx.x * blockDim.x + threadIdx.x;
    if (i < n) p[i] = 0.0f;
}

__global__ void degree_count_kernel(const int* __restrict__ src,
                                    const int* __restrict__ dst,
                                    float* __restrict__ rs_out,
                                    float* __restrict__ rs_in) {
    int i = blockIdx.x * blockDim.x + threadIdx.x;
    if (i >= RR * EE) return;
    int r = i / EE;
    atomicAdd(&rs_out[r * NN + src[i]], 1.0f);
    atomicAdd(&rs_in [r * NN + dst[i]], 1.0f);
}

__global__ void degree_finalize_kernel(float* p, int n) {
    int i = blockIdx.x * blockDim.x + threadIdx.x;
    if (i < n) p[i] = rsqrtf(fmaxf(p[i], 1.0f));
}

// acc[i] = sum_r b[r][f]
template <int F>
__global__ void init_bias_kernel(float* __restrict__ acc, const float* __restrict__ b) {
    int i = blockIdx.x * blockDim.x + threadIdx.x;
    if (i >= NN * F) return;
    int f = i % F;
    acc[i] = b[0 * F + f] + b[1 * F + f] + b[2 * F + f] + b[3 * F + f];
}

// Split fp32 -> (hi, lo) bf16 pair, optional fused ReLU. n % 4 == 0.
template <bool RELU>
__global__ void split_kernel(const float* __restrict__ in,
                             __nv_bfloat16* __restrict__ hi,
                             __nv_bfloat16* __restrict__ lo, int n) {
    int i4 = (blockIdx.x * blockDim.x + threadIdx.x) * 4;
    if (i4 >= n) return;
    float4 v = *reinterpret_cast<const float4*>(in + i4);
    if (RELU) {
        v.x = fmaxf(v.x, 0.f); v.y = fmaxf(v.y, 0.f);
        v.z = fmaxf(v.z, 0.f); v.w = fmaxf(v.w, 0.f);
    }
    __nv_bfloat16 hx = __float2bfloat16(v.x), hy = __float2bfloat16(v.y);
    __nv_bfloat16 hz = __float2bfloat16(v.z), hw = __float2bfloat16(v.w);
    float lx = v.x - __bfloat162float(hx), ly = v.y - __bfloat162float(hy);
    float lz = v.z - __bfloat162float(hz), lw = v.w - __bfloat162float(hw);
    __nv_bfloat162* H = reinterpret_cast<__nv_bfloat162*>(hi + i4);
    __nv_bfloat162* L = reinterpret_cast<__nv_bfloat162*>(lo + i4);
    H[0] = __halves2bfloat162(hx, hy);
    H[1] = __halves2bfloat162(hz, hw);
    L[0] = __halves2bfloat162(__float2bfloat16(lx), __float2bfloat16(ly));
    L[1] = __halves2bfloat162(__float2bfloat16(lz), __float2bfloat16(lw));
}

// ---------------------------------------------------------------------------
// Tensor-core GEMM (3-term bf16 split): Y[r][m, 0:BN] = A[m, :] @ W_r[:, 0:BN]
// BM=128, BK=32, 256 threads (8 warps: 4 m x 2 n), warp tile 32 x BN/2.
// blockIdx.y = relation.
// ---------------------------------------------------------------------------
template <int BN>
__global__ __launch_bounds__(256)
void gemm_bf16_kernel(const __nv_bfloat16* __restrict__ Ahi,
                      const __nv_bfloat16* __restrict__ Alo,
                      const __nv_bfloat16* __restrict__ Whi,
                      const __nv_bfloat16* __restrict__ Wlo,
                      float* __restrict__ Y,
                      int M, int K) {
    constexpr int BM = 128;
    constexpr int BK = 32;
    constexpr int NT = BN / 16;       // n-tiles (8 cols each) per warp
    constexpr int AS = BK + 8;        // smem strides (bank-conflict-free for ldmatrix)
    constexpr int BS = BN + 8;

    __shared__ __align__(16) __nv_bfloat16 sAh[BM * AS], sAl[BM * AS];
    __shared__ __align__(16) __nv_bfloat16 sBh[BK * BS], sBl[BK * BS];

    const int t = threadIdx.x;
    const int lane = t & 31;
    const int wid = t >> 5;
    const int wm = wid & 3;           // warp row (32 rows each)
    const int wn = wid >> 2;          // warp col (BN/2 cols each)
    const int rowBase = blockIdx.x * BM;
    const int rel = blockIdx.y;

    const __nv_bfloat16* WhiR = Whi + (size_t)rel * K * BN;
    const __nv_bfloat16* WloR = Wlo + (size_t)rel * K * BN;

    float acc[2][NT][4];
#pragma unroll
    for (int mt = 0; mt < 2; ++mt)
#pragma unroll
        for (int nt = 0; nt < NT; ++nt)
#pragma unroll
            for (int j = 0; j < 4; ++j) acc[mt][nt][j] = 0.f;

    for (int k0 = 0; k0 < K; k0 += BK) {
        // ---- A tiles (hi & lo): 128 rows x 32 cols, 8 bf16 per thread per array
#pragma unroll
        for (int i = 0; i < 2; ++i) {
            int id = t + i * 256;
            int row = id >> 2;
            int c8 = (id & 3) * 8;
            int gr = rowBase + row;
            uint4 vh = make_uint4(0, 0, 0, 0), vl = make_uint4(0, 0, 0, 0);
            if (gr < M) {
                vh = *reinterpret_cast<const uint4*>(Ahi + (size_t)gr * K + k0 + c8);
                vl = *reinterpret_cast<const uint4*>(Alo + (size_t)gr * K + k0 + c8);
            }
            *reinterpret_cast<uint4*>(&sAh[row * AS + c8]) = vh;
            *reinterpret_cast<uint4*>(&sAl[row * AS + c8]) = vl;
        }
        // ---- B tiles (hi & lo): 32 rows x BN cols
#pragma unroll
        for (int i = 0; i < (BK * BN / 8) / 256; ++i) {
            int id = t + i * 256;
            int row = id / (BN / 8);
            int c8 = (id % (BN / 8)) * 8;
            *reinterpret_cast<uint4*>(&sBh[row * BS + c8]) =
                *reinterpret_cast<const uint4*>(WhiR + (size_t)(k0 + row) * BN + c8);
            *reinterpret_cast<uint4*>(&sBl[row * BS + c8]) =
                *reinterpret_cast<const uint4*>(WloR + (size_t)(k0 + row) * BN + c8);
        }
        __syncthreads();

#pragma unroll
        for (int kk = 0; kk < BK; kk += 16) {
            uint32_t ah[2][4], al[2][4];
#pragma unroll
            for (int mt = 0; mt < 2; ++mt) {
                int row = wm * 32 + mt * 16 + (lane & 15);
                int col = kk + (lane >> 4) * 8;
                ldsm_x4(ah[mt], (uint32_t)__cvta_generic_to_shared(&sAh[row * AS + col]));
                ldsm_x4(al[mt], (uint32_t)__cvta_generic_to_shared(&sAl[row * AS + col]));
            }
            uint32_t bh[NT][2], bl[NT][2];
#pragma unroll
            for (int nt = 0; nt < NT; ++nt) {
                int col = wn * (BN / 2) + nt * 8;
                int row = kk + (lane & 15);
                ldsm_x2t(bh[nt], (uint32_t)__cvta_generic_to_shared(&sBh[row * BS + col]));
                ldsm_x2t(bl[nt], (uint32_t)__cvta_generic_to_shared(&sBl[row * BS + col]));
            }
#pragma unroll
            for (int mt = 0; mt < 2; ++mt)
#pragma unroll
                for (int nt = 0; nt < NT; ++nt) {
                    mma16816(acc[mt][nt], ah[mt], bh[nt]);   // hi*hi
                    mma16816(acc[mt][nt], al[mt], bh[nt]);   // lo*hi
                    mma16816(acc[mt][nt], ah[mt], bl[nt]);   // hi*lo
                }
        }
        __syncthreads();
    }

    // ---- epilogue: D frag thread map: c0,c1 -> (l/4, (l%4)*2), c2,c3 -> row+8
#pragma unroll
    for (int mt = 0; mt < 2; ++mt) {
        int gr0 = rowBase + wm * 32 + mt * 16 + (lane >> 2);
        int gc0 = wn * (BN / 2) + (lane & 3) * 2;
#pragma unroll
        for (int nt = 0; nt < NT; ++nt) {
            int c = gc0 + nt * 8;
            if (gr0 < M)
                *reinterpret_cast<float2*>(Y + ((size_t)rel * NN + gr0) * BN + c) =
                    make_float2(acc[mt][nt][0], acc[mt][nt][1]);
            if (gr0 + 8 < M)
                *reinterpret_cast<float2*>(Y + ((size_t)rel * NN + gr0 + 8) * BN + c) =
                    make_float2(acc[mt][nt][2], acc[mt][nt][3]);
        }
    }
}

// ---------------------------------------------------------------------------
// Edge scatter, all relations in one launch, vector REDs.
// acc[d] += rs_out_r[s] * rs_in_r[d] * Y[r][s, :]
// ---------------------------------------------------------------------------
__global__ __launch_bounds__(256)
void scatter_f128_kernel(const float* __restrict__ Y,
                         const int* __restrict__ esrc,
                         const int* __restrict__ edst,
                         const float* __restrict__ rs_out,
                         const float* __restrict__ rs_in,
                         float* __restrict__ acc) {
    int gw = (blockIdx.x * blockDim.x + threadIdx.x) >> 5;
    int lane = threadIdx.x & 31;
    if (gw >= RR * EE) return;
    int r = gw / EE;
    int s = esrc[gw];
    int d = edst[gw];
    float c = __ldg(&rs_out[r * NN + s]) * __ldg(&rs_in[r * NN + d]);
    float4 v = *reinterpret_cast<const float4*>(Y + ((size_t)r * NN + s) * HIDF + lane * 4);
    float* p = acc + (size_t)d * HIDF + lane * 4;
    asm volatile("red.global.add.v4.f32 [%0], {%1,%2,%3,%4};"
                 :: "l"(p), "f"(c * v.x), "f"(c * v.y), "f"(c * v.z), "f"(c * v.w)
                 : "memory");
}

__global__ __launch_bounds__(256)
void scatter_f64_kernel(const float* __restrict__ Y,
                        const int* __restrict__ esrc,
                        const int* __restrict__ edst,
                        const float* __restrict__ rs_out,
                        const float* __restrict__ rs_in,
                        float* __restrict__ acc) {
    int gw = (blockIdx.x * blockDim.x + threadIdx.x) >> 5;
    int lane = threadIdx.x & 31;
    if (gw >= RR * EE) return;
    int r = gw / EE;
    int s = esrc[gw];
    int d = edst[gw];
    float c = __ldg(&rs_out[r * NN + s]) * __ldg(&rs_in[r * NN + d]);
    float2 v = *reinterpret_cast<const float2*>(Y + ((size_t)r * NN + s) * OUTF + lane * 2);
    float* p = acc + (size_t)d * OUTF + lane * 2;
    asm volatile("red.global.add.v2.f32 [%0], {%1,%2};"
                 :: "l"(p), "f"(c * v.x), "f"(c * v.y)
                 : "memory");
}

// ---------------------------------------------------------------------------
// Launch
// ---------------------------------------------------------------------------
extern "C" void kernel_launch(void* const* d_in, const int* in_sizes, int n_in,
                              void* d_out, int out_size) {
    const float* x    = (const float*)d_in[0];
    const int*   esrc = (const int*)  d_in[1];
    const int*   edst = (const int*)  d_in[2];
    const float* W1   = (const float*)d_in[3];
    const float* b1   = (const float*)d_in[4];
    const float* W2   = (const float*)d_in[5];
    const float* b2   = (const float*)d_in[6];
    float* out = (float*)d_out;

    __nv_bfloat16 *xhi, *xlo, *w1hi, *w1lo, *w2hi, *w2lo, *a2hi, *a2lo;
    float *Y1, *Y2, *acc1, *rs;
    cudaGetSymbolAddress((void**)&xhi,  g_xhi);
    cudaGetSymbolAddress((void**)&xlo,  g_xlo);
    cudaGetSymbolAddress((void**)&w1hi, g_w1hi);
    cudaGetSymbolAddress((void**)&w1lo, g_w1lo);
    cudaGetSymbolAddress((void**)&w2hi, g_w2hi);
    cudaGetSymbolAddress((void**)&w2lo, g_w2lo);
    cudaGetSymbolAddress((void**)&a2hi, g_a2hi);
    cudaGetSymbolAddress((void**)&a2lo, g_a2lo);
    cudaGetSymbolAddress((void**)&Y1,   g_Y1);
    cudaGetSymbolAddress((void**)&Y2,   g_Y2);
    cudaGetSymbolAddress((void**)&acc1, g_acc1);
    cudaGetSymbolAddress((void**)&rs,   g_rs);
    float* rs_out = rs;
    float* rs_in  = rs + RR * NN;

    const int TPB = 256;

    // ---- degrees ----
    {
        int n = 2 * RR * NN;
        fzero_kernel<<<(n + TPB - 1) / TPB, TPB>>>(rs, n);
        degree_count_kernel<<<(RR * EE + TPB - 1) / TPB, TPB>>>(esrc, edst, rs_out, rs_in);
        degree_finalize_kernel<<<(n + TPB - 1) / TPB, TPB>>>(rs, n);
    }

    // ---- bf16 splits of inputs/weights ----
    {
        int nx = NN * INF;
        split_kernel<false><<<(nx / 4 + TPB - 1) / TPB, TPB>>>(x, xhi, xlo, nx);
        int nw1 = RR * INF * HIDF;
        split_kernel<false><<<(nw1 / 4 + TPB - 1) / TPB, TPB>>>(W1, w1hi, w1lo, nw1);
        int nw2 = RR * HIDF * OUTF;
        split_kernel<false><<<(nw2 / 4 + TPB - 1) / TPB, TPB>>>(W2, w2hi, w2lo, nw2);
    }

    const dim3 gemmGrid((NN + 127) / 128, RR);
    const int scatterGrid = (RR * EE * 32 + TPB - 1) / TPB;

    // ---- Layer 1 ----
    init_bias_kernel<HIDF><<<(NN * HIDF + TPB - 1) / TPB, TPB>>>(acc1, b1);
    gemm_bf16_kernel<HIDF><<<gemmGrid, TPB>>>(xhi, xlo, w1hi, w1lo, Y1, NN, INF);
    scatter_f128_kernel<<<scatterGrid, TPB>>>(Y1, esrc, edst, rs_out, rs_in, acc1);

    // ---- ReLU + split for layer 2 ----
    {
        int n = NN * HIDF;
        split_kernel<true><<<(n / 4 + TPB - 1) / TPB, TPB>>>(acc1, a2hi, a2lo, n);
    }

    // ---- Layer 2 ----
    init_bias_kernel<OUTF><<<(NN * OUTF + TPB - 1) / TPB, TPB>>>(out, b2);
    gemm_bf16_kernel<OUTF><<<gemmGrid, TPB>>>(a2hi, a2lo, w2hi, w2lo, Y2, NN, HIDF);
    scatter_f64_kernel<<<scatterGrid, TPB>>>(Y2, esrc, edst, rs_out, rs_in, out);
}